// round 15
// baseline (speedup 1.0000x reference)
#include <cuda_runtime.h>
#include <cuda_bf16.h>
#include <cuda_fp16.h>
#include <math.h>
#include <stdint.h>

#define SEQ    4096
#define BATCH  4
#define HID    1024
#define NH     16
#define HD     64
#define BHD    (BATCH * NH)     // 64
#define WIN    257
#define HALF   128
#define MINSC  (-1e9f)
#define ROWS   (SEQ * BATCH)    // 16384

// ---------------- scratch (device globals; no allocation allowed) ------------
__device__ __nv_bfloat16 g_ph[3ull * BHD * SEQ * HD];
__device__ __nv_bfloat16 g_pl[3ull * BHD * SEQ * HD];
__device__ __half        g_vf16[(size_t)BHD * SEQ * HD];

__device__ __nv_bfloat16 g_xhi[3ull * ROWS * HID];
__device__ __nv_bfloat16 g_xlo[3ull * ROWS * HID];
__device__ __nv_bfloat16 g_whi[3ull * HID * HID];
__device__ __nv_bfloat16 g_wlo[3ull * HID * HID];
__device__ __half        g_xvf[(size_t)ROWS * HID];   // value input, fp16
__device__ __half        g_wvf[(size_t)HID * HID];    // Wv, fp16

// ================= small PTX helpers ========================================
__device__ __forceinline__ uint32_t smem_u32(const void* p) {
    uint32_t a;
    asm("{ .reg .u64 t; cvta.to.shared.u64 t, %1; cvt.u32.u64 %0, t; }"
        : "=r"(a) : "l"(p));
    return a;
}
__device__ __forceinline__ void cp16(uint32_t s, const void* g) {
    asm volatile("cp.async.cg.shared.global [%0], [%1], 16;" :: "r"(s), "l"(g));
}
__device__ __forceinline__ void cp16z(uint32_t s, const void* g, int sz) {
    asm volatile("cp.async.cg.shared.global [%0], [%1], 16, %2;"
                 :: "r"(s), "l"(g), "r"(sz));
}
#define CP_COMMIT() asm volatile("cp.async.commit_group;" ::: "memory")
#define CP_WAIT1()  asm volatile("cp.async.wait_group 1;" ::: "memory")
#define CP_WAIT0()  asm volatile("cp.async.wait_group 0;" ::: "memory")

__device__ __forceinline__ void ldm_x4(uint32_t* r, uint32_t addr) {
    asm volatile("ldmatrix.sync.aligned.m8n8.x4.shared.b16 {%0,%1,%2,%3}, [%4];"
        : "=r"(r[0]), "=r"(r[1]), "=r"(r[2]), "=r"(r[3]) : "r"(addr));
}
__device__ __forceinline__ void ldm_x4_t(uint32_t* r, uint32_t addr) {
    asm volatile("ldmatrix.sync.aligned.m8n8.x4.trans.shared.b16 {%0,%1,%2,%3}, [%4];"
        : "=r"(r[0]), "=r"(r[1]), "=r"(r[2]), "=r"(r[3]) : "r"(addr));
}
__device__ __forceinline__ void mma_bf16(float* c, const uint32_t* a,
                                         uint32_t b0, uint32_t b1) {
    asm volatile(
        "mma.sync.aligned.m16n8k16.row.col.f32.bf16.bf16.f32 "
        "{%0,%1,%2,%3}, {%4,%5,%6,%7}, {%8,%9}, {%0,%1,%2,%3};"
        : "+f"(c[0]), "+f"(c[1]), "+f"(c[2]), "+f"(c[3])
        : "r"(a[0]), "r"(a[1]), "r"(a[2]), "r"(a[3]), "r"(b0), "r"(b1));
}
__device__ __forceinline__ void mma_f16(float* c, const uint32_t* a,
                                        uint32_t b0, uint32_t b1) {
    asm volatile(
        "mma.sync.aligned.m16n8k16.row.col.f32.f16.f16.f32 "
        "{%0,%1,%2,%3}, {%4,%5,%6,%7}, {%8,%9}, {%0,%1,%2,%3};"
        : "+f"(c[0]), "+f"(c[1]), "+f"(c[2]), "+f"(c[3])
        : "r"(a[0]), "r"(a[1]), "r"(a[2]), "r"(a[3]), "r"(b0), "r"(b1));
}
__device__ __forceinline__ uint32_t pk2(float x, float y) {
    __nv_bfloat162 t;
    t.x = __float2bfloat16(x);
    t.y = __float2bfloat16(y);
    return *(uint32_t*)&t;
}
__device__ __forceinline__ uint32_t pk2r(float x, float y, uint32_t h) {
    const __nv_bfloat162 hh = *(__nv_bfloat162*)&h;
    __nv_bfloat162 t;
    t.x = __float2bfloat16(x - __bfloat162float(hh.x));
    t.y = __float2bfloat16(y - __bfloat162float(hh.y));
    return *(uint32_t*)&t;
}
__device__ __forceinline__ uint32_t pkh2(float x, float y) {
    __half2 t;
    t.x = __float2half_rn(x);
    t.y = __float2half_rn(y);
    return *(uint32_t*)&t;
}

// ================= merged conversion kernel =================================
#define XBLK (ROWS * HID / 4 / 256)   // 16384
#define WBLK (HID * HID / 4 / 256)    // 1024

__global__ __launch_bounds__(256) void convert_all(
    const float* __restrict__ q, const float* __restrict__ k, const float* __restrict__ v,
    const float* __restrict__ wq, const float* __restrict__ wk, const float* __restrict__ wv)
{
    const int z = blockIdx.y;
    const int bx = blockIdx.x;
    if (bx < XBLK) {
        const float* src = (z == 0) ? q : (z == 1) ? k : v;
        const size_t i4 = (size_t)bx * 256 + threadIdx.x;
        const float4 x = ((const float4*)src)[i4];
        const float f[4] = {x.x, x.y, x.z, x.w};
        if (z == 2) {
            __half h[4];
#pragma unroll
            for (int j = 0; j < 4; j++) h[j] = __float2half_rn(f[j]);
            *(uint2*)(g_xvf + i4 * 4) = *(const uint2*)h;
        } else {
            __nv_bfloat16 h[4], l[4];
#pragma unroll
            for (int j = 0; j < 4; j++) {
                h[j] = __float2bfloat16(f[j]);
                l[j] = __float2bfloat16(f[j] - __bfloat162float(h[j]));
            }
            const size_t off = (size_t)z * ROWS * HID + i4 * 4;
            *(uint2*)(g_xhi + off) = *(const uint2*)h;
            *(uint2*)(g_xlo + off) = *(const uint2*)l;
        }
    } else {
        const float* src = (z == 0) ? wq : (z == 1) ? wk : wv;
        const size_t i4 = (size_t)(bx - XBLK) * 256 + threadIdx.x;
        const float4 x = ((const float4*)src)[i4];
        const float f[4] = {x.x, x.y, x.z, x.w};
        if (z == 2) {
            __half h[4];
#pragma unroll
            for (int j = 0; j < 4; j++) h[j] = __float2half_rn(f[j]);
            *(uint2*)(g_wvf + i4 * 4) = *(const uint2*)h;
        } else {
            __nv_bfloat16 h[4], l[4];
#pragma unroll
            for (int j = 0; j < 4; j++) {
                h[j] = __float2bfloat16(f[j]);
                l[j] = __float2bfloat16(f[j] - __bfloat162float(h[j]));
            }
            const size_t off = (size_t)z * HID * HID + i4 * 4;
            *(uint2*)(g_whi + off) = *(const uint2*)h;
            *(uint2*)(g_wlo + off) = *(const uint2*)l;
        }
    }
}

// ================= mma.sync projection GEMM =================================
// 256 threads, 8 warps = 2(m) x 4(n); warp tile 64x32; CTA 128x128, BK=32.
// z==0,1 (Q,K): bf16x3 (3 products). z==2 (V): single fp16 product.
#define PBM 128
#define PBN 128
#define PBK 32
#define RSTB 80
#define TILEB (PBM * RSTB)          // 10240
#define STAGEB (4 * TILEB)          // 40960
#define PROJ_SMEM (2 * STAGEB)      // 81920
#define NKT (HID / PBK)             // 32

__global__ __launch_bounds__(256, 2) void proj_mma_kernel(
    const float* __restrict__ bq, const float* __restrict__ bk, const float* __restrict__ bv)
{
    const int z   = blockIdx.z;
    const bool isV = (z == 2);
    const int bn0 = blockIdx.x * PBN;
    const int bm0 = blockIdx.y * PBM;
    const float* Bias = (z == 0) ? bq : (z == 1) ? bk : bv;
    const size_t zoff = (size_t)z * BHD * SEQ * HD;
    const __nv_bfloat16* Xhi = g_xhi + (size_t)z * ROWS * HID;
    const __nv_bfloat16* Xlo = g_xlo + (size_t)z * ROWS * HID;
    const __nv_bfloat16* Whi = g_whi + (size_t)z * HID * HID;
    const __nv_bfloat16* Wlo = g_wlo + (size_t)z * HID * HID;

    extern __shared__ char smc[];
    const uint32_t sb = smem_u32(smc);

    const int tid  = threadIdx.x;
    const int warp = tid >> 5;
    const int lane = tid & 31;
    const int mw   = warp >> 2;
    const int nw   = warp & 3;
    const int l4   = lane >> 2, lm = lane & 3;

    auto load_stage = [&](int st, int k0) {
        const uint32_t base = sb + st * STAGEB;
        if (isV) {
#pragma unroll
            for (int i = 0; i < 2; i++) {
                const int idx = tid + 256 * i;
                const int row = idx >> 2;
                const int g   = idx & 3;
                cp16(base + row * RSTB + g * 16,
                     g_xvf + (size_t)(bm0 + row) * HID + k0 + g * 8);
                cp16(base + 2 * TILEB + row * RSTB + g * 16,
                     g_wvf + (size_t)(bn0 + row) * HID + k0 + g * 8);
            }
        } else {
            const __nv_bfloat16* srcs[4] = {Xhi, Xlo, Whi, Wlo};
            const int rb[4] = {bm0, bm0, bn0, bn0};
#pragma unroll
            for (int t = 0; t < 4; t++) {
#pragma unroll
                for (int i = 0; i < 2; i++) {
                    const int idx = tid + 256 * i;
                    const int row = idx >> 2;
                    const int g   = idx & 3;
                    cp16(base + t * TILEB + row * RSTB + g * 16,
                         srcs[t] + (size_t)(rb[t] + row) * HID + k0 + g * 8);
                }
            }
        }
    };

    float c[4][4][4];
#pragma unroll
    for (int i = 0; i < 4; i++)
#pragma unroll
        for (int j = 0; j < 4; j++)
#pragma unroll
            for (int e = 0; e < 4; e++) c[i][j][e] = 0.f;

    load_stage(0, 0);
    CP_COMMIT();

    const uint32_t a_off = (uint32_t)(lane & 15) * RSTB + (uint32_t)(lane >> 4) * 16;
    const uint32_t b_off = (uint32_t)((((lane >> 4) & 1) << 3) + (lane & 7)) * RSTB
                         + (uint32_t)((lane >> 3) & 1) * 16;

    for (int kt = 0; kt < NKT; kt++) {
        if (kt + 1 < NKT) load_stage((kt + 1) & 1, (kt + 1) * PBK);
        CP_COMMIT();
        CP_WAIT1();
        __syncthreads();

        const uint32_t stb = sb + (kt & 1) * STAGEB;
        const uint32_t Ab = stb + (uint32_t)(mw * 64) * RSTB + a_off;
        const uint32_t Bb = stb + 2 * TILEB + (uint32_t)(nw * 32) * RSTB + b_off;

        if (isV) {
#pragma unroll
            for (int ks = 0; ks < 2; ks++) {
                const uint32_t ko = ks * 32;
                uint32_t Bh[4][2];
#pragma unroll
                for (int jp = 0; jp < 2; jp++) {
                    uint32_t rh[4];
                    ldm_x4(rh, Bb + jp * 16 * RSTB + ko);
                    Bh[jp * 2 + 0][0] = rh[0]; Bh[jp * 2 + 0][1] = rh[1];
                    Bh[jp * 2 + 1][0] = rh[2]; Bh[jp * 2 + 1][1] = rh[3];
                }
#pragma unroll
                for (int mt = 0; mt < 4; mt++) {
                    uint32_t Ah[4];
                    ldm_x4(Ah, Ab + mt * 16 * RSTB + ko);
#pragma unroll
                    for (int nt = 0; nt < 4; nt++)
                        mma_f16(c[mt][nt], Ah, Bh[nt][0], Bh[nt][1]);
                }
            }
        } else {
#pragma unroll
            for (int ks = 0; ks < 2; ks++) {
                const uint32_t ko = ks * 32;
                uint32_t Bh[4][2], Bl[4][2];
#pragma unroll
                for (int jp = 0; jp < 2; jp++) {
                    uint32_t rh[4], rl[4];
                    ldm_x4(rh, Bb + jp * 16 * RSTB + ko);
                    ldm_x4(rl, Bb + TILEB + jp * 16 * RSTB + ko);
                    Bh[jp * 2 + 0][0] = rh[0]; Bh[jp * 2 + 0][1] = rh[1];
                    Bh[jp * 2 + 1][0] = rh[2]; Bh[jp * 2 + 1][1] = rh[3];
                    Bl[jp * 2 + 0][0] = rl[0]; Bl[jp * 2 + 0][1] = rl[1];
                    Bl[jp * 2 + 1][0] = rl[2]; Bl[jp * 2 + 1][1] = rl[3];
                }
#pragma unroll
                for (int mt = 0; mt < 4; mt++) {
                    uint32_t Ah[4], Al[4];
                    ldm_x4(Ah, Ab + mt * 16 * RSTB + ko);
                    ldm_x4(Al, Ab + TILEB + mt * 16 * RSTB + ko);
#pragma unroll
                    for (int nt = 0; nt < 4; nt++) {
                        mma_bf16(c[mt][nt], Ah, Bh[nt][0], Bh[nt][1]);
                        mma_bf16(c[mt][nt], Al, Bh[nt][0], Bh[nt][1]);
                        mma_bf16(c[mt][nt], Ah, Bl[nt][0], Bl[nt][1]);
                    }
                }
            }
        }
        __syncthreads();
    }

    // ---- epilogue: bias + split -> smem stage -> coalesced stores ----------
    uint32_t* HI = (uint32_t*)smc;
    uint32_t* LO = HI + 128 * 66;

#pragma unroll
    for (int mt = 0; mt < 4; mt++)
#pragma unroll
        for (int nt = 0; nt < 4; nt++) {
            const int col = bn0 + nw * 32 + nt * 8 + 2 * lm;
            const float bi0 = Bias[col], bi1 = Bias[col + 1];
            const int cp = nw * 16 + nt * 4 + lm;
#pragma unroll
            for (int eh = 0; eh < 2; eh++) {
                const int r = mw * 64 + mt * 16 + l4 + eh * 8;
                const float v0 = c[mt][nt][eh * 2 + 0] + bi0;
                const float v1 = c[mt][nt][eh * 2 + 1] + bi1;
                if (z == 2) {
                    HI[r * 66 + cp] = pkh2(v0, v1);
                } else {
                    const uint32_t hh = pk2(v0, v1);
                    HI[r * 66 + cp] = hh;
                    LO[r * 66 + cp] = pk2r(v0, v1, hh);
                }
            }
        }
    __syncthreads();

    {
        const int j = lane & 15;
#pragma unroll 4
        for (int it = 0; it < 32; it++) {
            const int seg  = it * 16 + warp * 2 + (lane >> 4);
            const int r    = seg & 127;
            const int pick = seg >> 7;
            const int hd2  = pick >> 1;
            const int hl   = pick & 1;
            const int rg = bm0 + r;
            const int s = rg >> 2, bb = rg & 3;
            const int headidx = blockIdx.x * 2 + hd2;
            if (z == 2) {
                if (hl == 0) {
                    const uint32_t* src = HI + r * 66 + hd2 * 32 + j * 2;
                    __half* dstp = g_vf16
                        + ((size_t)(bb * NH + headidx) * SEQ + s) * HD + j * 4;
                    *(uint2*)dstp = *(const uint2*)src;
                }
            } else {
                const uint32_t* src = (hl ? LO : HI) + r * 66 + hd2 * 32 + j * 2;
                __nv_bfloat16* dstp = (hl ? g_pl : g_ph) + zoff
                    + ((size_t)(bb * NH + headidx) * SEQ + s) * HD + j * 4;
                *(uint2*)dstp = *(const uint2*)src;
            }
        }
    }
}

// ================= tensor-core local attention v8 ===========================
// v7 + mt-granular (16-row) band skip in GEMM1.
#define TQ   64
#define WR   320
#define KSTB 144
#define PSTB 656

#define S_KH   0
#define S_KL   46080
#define S_VF   0
#define S_PF   46080
#define S_QH   92160
#define S_QL   101376
#define S_MSK  110592
#define S_RMAX 110976
#define S_RSUM 112000
#define ATT_SMEM 113024

__global__ __launch_bounds__(256, 2) void attn_kernel(
    const unsigned char* __restrict__ mask,
    float* __restrict__ out, float* __restrict__ probs)
{
    const int bh   = blockIdx.y;
    const int s0   = blockIdx.x * TQ;
    const int b    = bh >> 4;
    const int head = bh & 15;
    const int base = s0 - HALF;

    const __nv_bfloat16* Qh = g_ph + (size_t)(0 * BHD + bh) * SEQ * HD;
    const __nv_bfloat16* Ql = g_pl + (size_t)(0 * BHD + bh) * SEQ * HD;
    const __nv_bfloat16* Kh = g_ph + (size_t)(1 * BHD + bh) * SEQ * HD;
    const __nv_bfloat16* Kl = g_pl + (size_t)(1 * BHD + bh) * SEQ * HD;
    const __half*        Vf = g_vf16 + (size_t)bh * SEQ * HD;

    extern __shared__ char smc[];
    const uint32_t sb = smem_u32(smc);
    unsigned char* msh = (unsigned char*)(smc + S_MSK);

    const int tid  = threadIdx.x;
    const int warp = tid >> 5;
    const int lane = tid & 31;
    const int lane4 = lane >> 2, lanem = lane & 3;

    for (int o = tid; o < WR; o += 256) {
        const int t = base + o;
        msh[o] = (t >= 0 && t < SEQ && mask[t * BATCH + b] == 0) ? 1 : 0;
    }
#pragma unroll
    for (int it = 0; it < 10; it++) {
        const int idx = tid + 256 * it;
        const int row = idx >> 3, g = idx & 7;
        const int t = base + row;
        const int ok = (t >= 0 && t < SEQ);
        const int tc = ok ? t : 0;
        const int sz = ok ? 16 : 0;
        cp16z(sb + S_KH + row * KSTB + g * 16, Kh + (size_t)tc * HD + g * 8, sz);
        cp16z(sb + S_KL + row * KSTB + g * 16, Kl + (size_t)tc * HD + g * 8, sz);
    }
#pragma unroll
    for (int it = 0; it < 2; it++) {
        const int idx = tid + 256 * it;
        const int row = idx >> 3, g = idx & 7;
        cp16(sb + S_QH + row * KSTB + g * 16, Qh + (size_t)(s0 + row) * HD + g * 8);
        cp16(sb + S_QL + row * KSTB + g * 16, Ql + (size_t)(s0 + row) * HD + g * 8);
    }
    CP_COMMIT();
    CP_WAIT0();
    __syncthreads();

    // ---- GEMM1: S = Q K^T (bf16x3) with 16-row-granular band-skip ----
    const int mw = warp >> 2;
    const int nw = warp & 3;
    const uint32_t a_off = (uint32_t)(lane & 15) * KSTB + (uint32_t)(lane >> 4) * 16;
    const uint32_t b_off = (uint32_t)((((lane >> 4) & 1) << 3) + (lane & 7)) * KSTB
                         + (uint32_t)((lane >> 3) & 1) * 16;

    float c1[2][10][4];
#pragma unroll
    for (int i = 0; i < 2; i++)
#pragma unroll
        for (int j = 0; j < 10; j++)
#pragma unroll
            for (int e = 0; e < 4; e++) c1[i][j][e] = 0.f;

#pragma unroll
    for (int kt = 0; kt < 4; kt++) {
        uint32_t Ah[2][4], Al[2][4];
#pragma unroll
        for (int mt = 0; mt < 2; mt++) {
            const uint32_t qa = sb + S_QH + (uint32_t)(mw * 32 + mt * 16) * KSTB
                              + a_off + kt * 32;
            ldm_x4(Ah[mt], qa);
            ldm_x4(Al[mt], qa + (S_QL - S_QH));
        }
#pragma unroll
        for (int np = 0; np < 5; np++) {
            const int cL = nw * 80 + np * 16;
            // per-16-row-tile validity: rows [R, R+15] need cols [R, R+271]
            const int R0 = mw * 32;           // mt = 0
            const int R1 = mw * 32 + 16;      // mt = 1
            const bool v0 = !(cL + 15 < R0 || cL > R0 + 271);
            const bool v1 = !(cL + 15 < R1 || cL > R1 + 271);
            if (!v0 && !v1) continue;
            const uint32_t ka = sb + S_KH + (uint32_t)(cL) * KSTB
                              + b_off + kt * 32;
            uint32_t rh[4], rl[4];
            ldm_x4(rh, ka);
            ldm_x4(rl, ka + (S_KL - S_KH));
#pragma unroll
            for (int j = 0; j < 2; j++) {
                const int nt = np * 2 + j;
                const uint32_t bh0 = rh[2 * j], bh1 = rh[2 * j + 1];
                const uint32_t bl0 = rl[2 * j], bl1 = rl[2 * j + 1];
                if (v0) {
                    mma_bf16(c1[0][nt], Ah[0], bh0, bh1);
                    mma_bf16(c1[0][nt], Al[0], bh0, bh1);
                    mma_bf16(c1[0][nt], Ah[0], bl0, bl1);
                }
                if (v1) {
                    mma_bf16(c1[1][nt], Ah[1], bh0, bh1);
                    mma_bf16(c1[1][nt], Al[1], bh0, bh1);
                    mma_bf16(c1[1][nt], Ah[1], bl0, bl1);
                }
            }
        }
    }
    __syncthreads();

#pragma unroll
    for (int it = 0; it < 10; it++) {
        const int idx = tid + 256 * it;
        const int row = idx >> 3, g = idx & 7;
        const int t = base + row;
        const int ok = (t >= 0 && t < SEQ);
        const int tc = ok ? t : 0;
        const int sz = ok ? 16 : 0;
        cp16z(sb + S_VF + row * KSTB + g * 16, Vf + (size_t)tc * HD + g * 8, sz);
    }
    CP_COMMIT();

    // ---- band/mask epilogue on fragments ----
    const int r0w = mw * 32 + lane4;
    const int c0w = nw * 80 + 2 * lanem;
    uint32_t vb[2][2] = {{0u, 0u}, {0u, 0u}};
#pragma unroll
    for (int mt = 0; mt < 2; mt++)
#pragma unroll
        for (int nt = 0; nt < 10; nt++)
#pragma unroll
            for (int e = 0; e < 4; e++) {
                const int eh = e >> 1, el = e & 1;
                const int r = r0w + mt * 16 + eh * 8;
                const int cc = c0w + nt * 8 + el;
                float s = c1[mt][nt][e];
                const bool inband = (cc >= r) && (cc <= r + 256);
                const bool valid  = inband && msh[cc];
                if (!inband)      s = -1e30f;
                else if (!valid)  s = MINSC;
                c1[mt][nt][e] = s;
                if (valid) vb[mt][eh] |= 1u << (nt * 2 + el);
            }

    // ---- online softmax: warp-local max + exp + local sums, ONE barrier ----
    float pm[2][2] = {{-3e38f, -3e38f}, {-3e38f, -3e38f}};
#pragma unroll
    for (int mt = 0; mt < 2; mt++)
#pragma unroll
        for (int nt = 0; nt < 10; nt++)
#pragma unroll
            for (int e = 0; e < 4; e++)
                pm[mt][e >> 1] = fmaxf(pm[mt][e >> 1], c1[mt][nt][e]);
#pragma unroll
    for (int mt = 0; mt < 2; mt++)
#pragma unroll
        for (int eh = 0; eh < 2; eh++) {
            pm[mt][eh] = fmaxf(pm[mt][eh], __shfl_xor_sync(0xffffffffu, pm[mt][eh], 1));
            pm[mt][eh] = fmaxf(pm[mt][eh], __shfl_xor_sync(0xffffffffu, pm[mt][eh], 2));
        }

    float ps[2][2] = {{0.f, 0.f}, {0.f, 0.f}};
#pragma unroll
    for (int mt = 0; mt < 2; mt++)
#pragma unroll
        for (int nt = 0; nt < 10; nt++)
#pragma unroll
            for (int e = 0; e < 4; e++) {
                const float ex = __expf(c1[mt][nt][e] - pm[mt][e >> 1]);
                c1[mt][nt][e] = ex;
                ps[mt][e >> 1] += ex;
            }
#pragma unroll
    for (int mt = 0; mt < 2; mt++)
#pragma unroll
        for (int eh = 0; eh < 2; eh++) {
            ps[mt][eh] += __shfl_xor_sync(0xffffffffu, ps[mt][eh], 1);
            ps[mt][eh] += __shfl_xor_sync(0xffffffffu, ps[mt][eh], 2);
        }
    if (lanem == 0) {
#pragma unroll
        for (int mt = 0; mt < 2; mt++)
#pragma unroll
            for (int eh = 0; eh < 2; eh++) {
                const int r = r0w + mt * 16 + eh * 8;
                *(float*)(smc + S_RMAX + (r * 4 + nw) * 4) = pm[mt][eh];
                *(float*)(smc + S_RSUM + (r * 4 + nw) * 4) = ps[mt][eh];
            }
    }
    __syncthreads();

    // ---- rescale to global softmax; write probs gmem + fp16 P smem ----
#pragma unroll
    for (int mt = 0; mt < 2; mt++)
#pragma unroll
        for (int eh = 0; eh < 2; eh++) {
            const int r = r0w + mt * 16 + eh * 8;
            const float* rp = (const float*)(smc + S_RMAX + r * 16);
            const float* sp = (const float*)(smc + S_RSUM + r * 16);
            const float gm = fmaxf(fmaxf(rp[0], rp[1]), fmaxf(rp[2], rp[3]));
            const float denom = sp[0] * __expf(rp[0] - gm)
                              + sp[1] * __expf(rp[1] - gm)
                              + sp[2] * __expf(rp[2] - gm)
                              + sp[3] * __expf(rp[3] - gm);
            const float sc = __expf(pm[mt][eh] - gm) / denom;
            float* prow = probs + ((size_t)bh * SEQ + (s0 + r)) * WIN;
            const uint32_t vbits = vb[mt][eh];
            char* pbf = smc + S_PF + r * PSTB;
#pragma unroll
            for (int nt = 0; nt < 10; nt++) {
                float p0 = c1[mt][nt][eh * 2 + 0] * sc;
                float p1 = c1[mt][nt][eh * 2 + 1] * sc;
                if (!(vbits & (1u << (nt * 2 + 0)))) p0 = 0.f;
                if (!(vbits & (1u << (nt * 2 + 1)))) p1 = 0.f;
                const int cc = c0w + nt * 8;
                if (cc >= r && cc <= r + 256)         prow[cc - r]     = p0;
                if (cc + 1 >= r && cc + 1 <= r + 256) prow[cc + 1 - r] = p1;
                *(uint32_t*)(pbf + cc * 2) = pkh2(p0, p1);
            }
        }

    CP_WAIT0();
    __syncthreads();

    // ---- GEMM2: O = P V (single fp16) with band-skip ----
    const int mw2 = warp >> 1;
    const int nw2 = warp & 1;
    float c2[4][4];
#pragma unroll
    for (int j = 0; j < 4; j++)
#pragma unroll
        for (int e = 0; e < 4; e++) c2[j][e] = 0.f;

    const uint32_t pa_off = (uint32_t)(lane & 15) * PSTB + (uint32_t)(lane >> 4) * 16;
    const uint32_t vrow   = (lane & 7) + (((lane >> 3) & 1) << 3);
    const uint32_t vcoff  = (uint32_t)(nw2 * 32 + ((lane >> 4) << 3)) * 2;

#pragma unroll 4
    for (int kt = 0; kt < 20; kt++) {
        const int kc = kt * 16;
        if (kc + 15 < mw2 * 16 || kc > mw2 * 16 + 271) continue;

        uint32_t Ph[4];
        ldm_x4(Ph, sb + S_PF + (uint32_t)(mw2 * 16) * PSTB + pa_off + kc * 2);

        uint32_t vh0[4], vh1[4];
        const uint32_t va = sb + S_VF + (kc + vrow) * KSTB + vcoff;
        ldm_x4_t(vh0, va);
        ldm_x4_t(vh1, va + 32);

#pragma unroll
        for (int nt = 0; nt < 4; nt++) {
            const uint32_t* ph = (nt < 2) ? vh0 : vh1;
            const int j = nt & 1;
            mma_f16(c2[nt], Ph, ph[2 * j], ph[2 * j + 1]);
        }
    }

#pragma unroll
    for (int nt = 0; nt < 4; nt++) {
        const int d = nw2 * 32 + nt * 8 + 2 * lanem;
#pragma unroll
        for (int eh = 0; eh < 2; eh++) {
            const int r = mw2 * 16 + lane4 + eh * 8;
            *(float2*)(out + ((size_t)(s0 + r) * BATCH + b) * HID + head * HD + d) =
                make_float2(c2[nt][eh * 2], c2[nt][eh * 2 + 1]);
        }
    }
}

// ---------------- launch ------------------------------------------------------
extern "C" void kernel_launch(void* const* d_in, const int* in_sizes, int n_in,
                              void* d_out, int out_size)
{
    const float* q_in = (const float*)d_in[0];
    const float* k_in = (const float*)d_in[1];
    const float* v_in = (const float*)d_in[2];
    const unsigned char* mask = (const unsigned char*)d_in[3];
    const float* Wq = (const float*)d_in[4];
    const float* bq = (const float*)d_in[5];
    const float* Wk = (const float*)d_in[6];
    const float* bk = (const float*)d_in[7];
    const float* Wv = (const float*)d_in[8];
    const float* bv = (const float*)d_in[9];

    float* out   = (float*)d_out;
    float* probs = out + (size_t)SEQ * BATCH * HID;

    cudaFuncSetAttribute(proj_mma_kernel, cudaFuncAttributeMaxDynamicSharedMemorySize,
                         PROJ_SMEM);
    cudaFuncSetAttribute(attn_kernel, cudaFuncAttributeMaxDynamicSharedMemorySize,
                         ATT_SMEM);

    dim3 gc(XBLK + WBLK, 3);
    convert_all<<<gc, 256>>>(q_in, k_in, v_in, Wq, Wk, Wv);

    dim3 gp(HID / PBN, ROWS / PBM, 3);
    proj_mma_kernel<<<gp, 256, PROJ_SMEM>>>(bq, bk, bv);

    dim3 ga(SEQ / TQ, BHD);
    attn_kernel<<<ga, 256, ATT_SMEM>>>(mask, out, probs);
}

// round 16
// speedup vs baseline: 1.0130x; 1.0130x over previous
#include <cuda_runtime.h>
#include <cuda_bf16.h>
#include <cuda_fp16.h>
#include <math.h>
#include <stdint.h>

#define SEQ    4096
#define BATCH  4
#define HID    1024
#define NH     16
#define HD     64
#define BHD    (BATCH * NH)     // 64
#define WIN    257
#define HALF   128
#define MINSC  (-1e9f)
#define ROWS   (SEQ * BATCH)    // 16384

// ---------------- scratch (device globals; no allocation allowed) ------------
__device__ __nv_bfloat16 g_ph[3ull * BHD * SEQ * HD];
__device__ __nv_bfloat16 g_pl[3ull * BHD * SEQ * HD];
__device__ __half        g_vf16[(size_t)BHD * SEQ * HD];

__device__ __nv_bfloat16 g_xhi[3ull * ROWS * HID];
__device__ __nv_bfloat16 g_xlo[3ull * ROWS * HID];
__device__ __nv_bfloat16 g_whi[3ull * HID * HID];
__device__ __nv_bfloat16 g_wlo[3ull * HID * HID];
__device__ __half        g_xvf[(size_t)ROWS * HID];   // value input, fp16
__device__ __half        g_wvf[(size_t)HID * HID];    // Wv, fp16

// ================= small PTX helpers ========================================
__device__ __forceinline__ uint32_t smem_u32(const void* p) {
    uint32_t a;
    asm("{ .reg .u64 t; cvta.to.shared.u64 t, %1; cvt.u32.u64 %0, t; }"
        : "=r"(a) : "l"(p));
    return a;
}
__device__ __forceinline__ void cp16(uint32_t s, const void* g) {
    asm volatile("cp.async.cg.shared.global [%0], [%1], 16;" :: "r"(s), "l"(g));
}
__device__ __forceinline__ void cp16z(uint32_t s, const void* g, int sz) {
    asm volatile("cp.async.cg.shared.global [%0], [%1], 16, %2;"
                 :: "r"(s), "l"(g), "r"(sz));
}
#define CP_COMMIT() asm volatile("cp.async.commit_group;" ::: "memory")
#define CP_WAIT1()  asm volatile("cp.async.wait_group 1;" ::: "memory")
#define CP_WAIT0()  asm volatile("cp.async.wait_group 0;" ::: "memory")

__device__ __forceinline__ void ldm_x4(uint32_t* r, uint32_t addr) {
    asm volatile("ldmatrix.sync.aligned.m8n8.x4.shared.b16 {%0,%1,%2,%3}, [%4];"
        : "=r"(r[0]), "=r"(r[1]), "=r"(r[2]), "=r"(r[3]) : "r"(addr));
}
__device__ __forceinline__ void ldm_x4_t(uint32_t* r, uint32_t addr) {
    asm volatile("ldmatrix.sync.aligned.m8n8.x4.trans.shared.b16 {%0,%1,%2,%3}, [%4];"
        : "=r"(r[0]), "=r"(r[1]), "=r"(r[2]), "=r"(r[3]) : "r"(addr));
}
__device__ __forceinline__ void mma_bf16(float* c, const uint32_t* a,
                                         uint32_t b0, uint32_t b1) {
    asm volatile(
        "mma.sync.aligned.m16n8k16.row.col.f32.bf16.bf16.f32 "
        "{%0,%1,%2,%3}, {%4,%5,%6,%7}, {%8,%9}, {%0,%1,%2,%3};"
        : "+f"(c[0]), "+f"(c[1]), "+f"(c[2]), "+f"(c[3])
        : "r"(a[0]), "r"(a[1]), "r"(a[2]), "r"(a[3]), "r"(b0), "r"(b1));
}
__device__ __forceinline__ void mma_f16(float* c, const uint32_t* a,
                                        uint32_t b0, uint32_t b1) {
    asm volatile(
        "mma.sync.aligned.m16n8k16.row.col.f32.f16.f16.f32 "
        "{%0,%1,%2,%3}, {%4,%5,%6,%7}, {%8,%9}, {%0,%1,%2,%3};"
        : "+f"(c[0]), "+f"(c[1]), "+f"(c[2]), "+f"(c[3])
        : "r"(a[0]), "r"(a[1]), "r"(a[2]), "r"(a[3]), "r"(b0), "r"(b1));
}
__device__ __forceinline__ uint32_t pk2(float x, float y) {
    __nv_bfloat162 t;
    t.x = __float2bfloat16(x);
    t.y = __float2bfloat16(y);
    return *(uint32_t*)&t;
}
__device__ __forceinline__ uint32_t pk2r(float x, float y, uint32_t h) {
    const __nv_bfloat162 hh = *(__nv_bfloat162*)&h;
    __nv_bfloat162 t;
    t.x = __float2bfloat16(x - __bfloat162float(hh.x));
    t.y = __float2bfloat16(y - __bfloat162float(hh.y));
    return *(uint32_t*)&t;
}
__device__ __forceinline__ uint32_t pkh2(float x, float y) {
    __half2 t;
    t.x = __float2half_rn(x);
    t.y = __float2half_rn(y);
    return *(uint32_t*)&t;
}

// ================= merged conversion kernel (16B-store version) =============
// Each thread handles 8 consecutive floats: 2x16B loads -> 16B hi + 16B lo
// stores (bf16) or one 16B fp16 store for the V stream.
#define XBLK8 (ROWS * HID / 8 / 256)   // 8192
#define WBLK8 (HID * HID / 8 / 256)    // 512

__global__ __launch_bounds__(256) void convert_all(
    const float* __restrict__ q, const float* __restrict__ k, const float* __restrict__ v,
    const float* __restrict__ wq, const float* __restrict__ wk, const float* __restrict__ wv)
{
    const int z = blockIdx.y;
    const int bx = blockIdx.x;
    const bool isX = (bx < XBLK8);
    const float* src = isX ? ((z == 0) ? q : (z == 1) ? k : v)
                           : ((z == 0) ? wq : (z == 1) ? wk : wv);
    const size_t i8 = ((size_t)(isX ? bx : bx - XBLK8) * 256 + threadIdx.x);

    const float4 x0 = ((const float4*)src)[i8 * 2 + 0];
    const float4 x1 = ((const float4*)src)[i8 * 2 + 1];
    const float f[8] = {x0.x, x0.y, x0.z, x0.w, x1.x, x1.y, x1.z, x1.w};

    if (z == 2) {
        __half h[8];
#pragma unroll
        for (int j = 0; j < 8; j++) h[j] = __float2half_rn(f[j]);
        if (isX) *(uint4*)(g_xvf + i8 * 8) = *(const uint4*)h;
        else     *(uint4*)(g_wvf + i8 * 8) = *(const uint4*)h;
    } else {
        __nv_bfloat16 h[8], l[8];
#pragma unroll
        for (int j = 0; j < 8; j++) {
            h[j] = __float2bfloat16(f[j]);
            l[j] = __float2bfloat16(f[j] - __bfloat162float(h[j]));
        }
        if (isX) {
            const size_t off = (size_t)z * ROWS * HID + i8 * 8;
            *(uint4*)(g_xhi + off) = *(const uint4*)h;
            *(uint4*)(g_xlo + off) = *(const uint4*)l;
        } else {
            const size_t off = (size_t)z * HID * HID + i8 * 8;
            *(uint4*)(g_whi + off) = *(const uint4*)h;
            *(uint4*)(g_wlo + off) = *(const uint4*)l;
        }
    }
}

// ================= mma.sync projection GEMM =================================
// 256 threads, 8 warps = 2(m) x 4(n); warp tile 64x32; CTA 128x128, BK=32.
// z==0,1 (Q,K): bf16x3 (3 products). z==2 (V): single fp16 product.
#define PBM 128
#define PBN 128
#define PBK 32
#define RSTB 80
#define TILEB (PBM * RSTB)          // 10240
#define STAGEB (4 * TILEB)          // 40960
#define PROJ_SMEM (2 * STAGEB)      // 81920
#define NKT (HID / PBK)             // 32

__global__ __launch_bounds__(256, 2) void proj_mma_kernel(
    const float* __restrict__ bq, const float* __restrict__ bk, const float* __restrict__ bv)
{
    const int z   = blockIdx.z;
    const bool isV = (z == 2);
    const int bn0 = blockIdx.x * PBN;
    const int bm0 = blockIdx.y * PBM;
    const float* Bias = (z == 0) ? bq : (z == 1) ? bk : bv;
    const size_t zoff = (size_t)z * BHD * SEQ * HD;
    const __nv_bfloat16* Xhi = g_xhi + (size_t)z * ROWS * HID;
    const __nv_bfloat16* Xlo = g_xlo + (size_t)z * ROWS * HID;
    const __nv_bfloat16* Whi = g_whi + (size_t)z * HID * HID;
    const __nv_bfloat16* Wlo = g_wlo + (size_t)z * HID * HID;

    extern __shared__ char smc[];
    const uint32_t sb = smem_u32(smc);

    const int tid  = threadIdx.x;
    const int warp = tid >> 5;
    const int lane = tid & 31;
    const int mw   = warp >> 2;
    const int nw   = warp & 3;
    const int l4   = lane >> 2, lm = lane & 3;

    auto load_stage = [&](int st, int k0) {
        const uint32_t base = sb + st * STAGEB;
        if (isV) {
#pragma unroll
            for (int i = 0; i < 2; i++) {
                const int idx = tid + 256 * i;
                const int row = idx >> 2;
                const int g   = idx & 3;
                cp16(base + row * RSTB + g * 16,
                     g_xvf + (size_t)(bm0 + row) * HID + k0 + g * 8);
                cp16(base + 2 * TILEB + row * RSTB + g * 16,
                     g_wvf + (size_t)(bn0 + row) * HID + k0 + g * 8);
            }
        } else {
            const __nv_bfloat16* srcs[4] = {Xhi, Xlo, Whi, Wlo};
            const int rb[4] = {bm0, bm0, bn0, bn0};
#pragma unroll
            for (int t = 0; t < 4; t++) {
#pragma unroll
                for (int i = 0; i < 2; i++) {
                    const int idx = tid + 256 * i;
                    const int row = idx >> 2;
                    const int g   = idx & 3;
                    cp16(base + t * TILEB + row * RSTB + g * 16,
                         srcs[t] + (size_t)(rb[t] + row) * HID + k0 + g * 8);
                }
            }
        }
    };

    float c[4][4][4];
#pragma unroll
    for (int i = 0; i < 4; i++)
#pragma unroll
        for (int j = 0; j < 4; j++)
#pragma unroll
            for (int e = 0; e < 4; e++) c[i][j][e] = 0.f;

    load_stage(0, 0);
    CP_COMMIT();

    const uint32_t a_off = (uint32_t)(lane & 15) * RSTB + (uint32_t)(lane >> 4) * 16;
    const uint32_t b_off = (uint32_t)((((lane >> 4) & 1) << 3) + (lane & 7)) * RSTB
                         + (uint32_t)((lane >> 3) & 1) * 16;

    for (int kt = 0; kt < NKT; kt++) {
        if (kt + 1 < NKT) load_stage((kt + 1) & 1, (kt + 1) * PBK);
        CP_COMMIT();
        CP_WAIT1();
        __syncthreads();

        const uint32_t stb = sb + (kt & 1) * STAGEB;
        const uint32_t Ab = stb + (uint32_t)(mw * 64) * RSTB + a_off;
        const uint32_t Bb = stb + 2 * TILEB + (uint32_t)(nw * 32) * RSTB + b_off;

        if (isV) {
#pragma unroll
            for (int ks = 0; ks < 2; ks++) {
                const uint32_t ko = ks * 32;
                uint32_t Bh[4][2];
#pragma unroll
                for (int jp = 0; jp < 2; jp++) {
                    uint32_t rh[4];
                    ldm_x4(rh, Bb + jp * 16 * RSTB + ko);
                    Bh[jp * 2 + 0][0] = rh[0]; Bh[jp * 2 + 0][1] = rh[1];
                    Bh[jp * 2 + 1][0] = rh[2]; Bh[jp * 2 + 1][1] = rh[3];
                }
#pragma unroll
                for (int mt = 0; mt < 4; mt++) {
                    uint32_t Ah[4];
                    ldm_x4(Ah, Ab + mt * 16 * RSTB + ko);
#pragma unroll
                    for (int nt = 0; nt < 4; nt++)
                        mma_f16(c[mt][nt], Ah, Bh[nt][0], Bh[nt][1]);
                }
            }
        } else {
#pragma unroll
            for (int ks = 0; ks < 2; ks++) {
                const uint32_t ko = ks * 32;
                uint32_t Bh[4][2], Bl[4][2];
#pragma unroll
                for (int jp = 0; jp < 2; jp++) {
                    uint32_t rh[4], rl[4];
                    ldm_x4(rh, Bb + jp * 16 * RSTB + ko);
                    ldm_x4(rl, Bb + TILEB + jp * 16 * RSTB + ko);
                    Bh[jp * 2 + 0][0] = rh[0]; Bh[jp * 2 + 0][1] = rh[1];
                    Bh[jp * 2 + 1][0] = rh[2]; Bh[jp * 2 + 1][1] = rh[3];
                    Bl[jp * 2 + 0][0] = rl[0]; Bl[jp * 2 + 0][1] = rl[1];
                    Bl[jp * 2 + 1][0] = rl[2]; Bl[jp * 2 + 1][1] = rl[3];
                }
#pragma unroll
                for (int mt = 0; mt < 4; mt++) {
                    uint32_t Ah[4], Al[4];
                    ldm_x4(Ah, Ab + mt * 16 * RSTB + ko);
                    ldm_x4(Al, Ab + TILEB + mt * 16 * RSTB + ko);
#pragma unroll
                    for (int nt = 0; nt < 4; nt++) {
                        mma_bf16(c[mt][nt], Ah, Bh[nt][0], Bh[nt][1]);
                        mma_bf16(c[mt][nt], Al, Bh[nt][0], Bh[nt][1]);
                        mma_bf16(c[mt][nt], Ah, Bl[nt][0], Bl[nt][1]);
                    }
                }
            }
        }
        __syncthreads();
    }

    // ---- epilogue: bias + split -> smem stage -> coalesced stores ----------
    uint32_t* HI = (uint32_t*)smc;
    uint32_t* LO = HI + 128 * 66;

#pragma unroll
    for (int mt = 0; mt < 4; mt++)
#pragma unroll
        for (int nt = 0; nt < 4; nt++) {
            const int col = bn0 + nw * 32 + nt * 8 + 2 * lm;
            const float bi0 = Bias[col], bi1 = Bias[col + 1];
            const int cp = nw * 16 + nt * 4 + lm;
#pragma unroll
            for (int eh = 0; eh < 2; eh++) {
                const int r = mw * 64 + mt * 16 + l4 + eh * 8;
                const float v0 = c[mt][nt][eh * 2 + 0] + bi0;
                const float v1 = c[mt][nt][eh * 2 + 1] + bi1;
                if (z == 2) {
                    HI[r * 66 + cp] = pkh2(v0, v1);
                } else {
                    const uint32_t hh = pk2(v0, v1);
                    HI[r * 66 + cp] = hh;
                    LO[r * 66 + cp] = pk2r(v0, v1, hh);
                }
            }
        }
    __syncthreads();

    {
        const int j = lane & 15;
#pragma unroll 4
        for (int it = 0; it < 32; it++) {
            const int seg  = it * 16 + warp * 2 + (lane >> 4);
            const int r    = seg & 127;
            const int pick = seg >> 7;
            const int hd2  = pick >> 1;
            const int hl   = pick & 1;
            const int rg = bm0 + r;
            const int s = rg >> 2, bb = rg & 3;
            const int headidx = blockIdx.x * 2 + hd2;
            if (z == 2) {
                if (hl == 0) {
                    const uint32_t* src = HI + r * 66 + hd2 * 32 + j * 2;
                    __half* dstp = g_vf16
                        + ((size_t)(bb * NH + headidx) * SEQ + s) * HD + j * 4;
                    *(uint2*)dstp = *(const uint2*)src;
                }
            } else {
                const uint32_t* src = (hl ? LO : HI) + r * 66 + hd2 * 32 + j * 2;
                __nv_bfloat16* dstp = (hl ? g_pl : g_ph) + zoff
                    + ((size_t)(bb * NH + headidx) * SEQ + s) * HD + j * 4;
                *(uint2*)dstp = *(const uint2*)src;
            }
        }
    }
}

// ================= tensor-core local attention v7 (round-14 form) ===========
#define TQ   64
#define WR   320
#define KSTB 144
#define PSTB 656

#define S_KH   0
#define S_KL   46080
#define S_VF   0
#define S_PF   46080
#define S_QH   92160
#define S_QL   101376
#define S_MSK  110592
#define S_RMAX 110976
#define S_RSUM 112000
#define ATT_SMEM 113024

__global__ __launch_bounds__(256, 2) void attn_kernel(
    const unsigned char* __restrict__ mask,
    float* __restrict__ out, float* __restrict__ probs)
{
    const int bh   = blockIdx.y;
    const int s0   = blockIdx.x * TQ;
    const int b    = bh >> 4;
    const int head = bh & 15;
    const int base = s0 - HALF;

    const __nv_bfloat16* Qh = g_ph + (size_t)(0 * BHD + bh) * SEQ * HD;
    const __nv_bfloat16* Ql = g_pl + (size_t)(0 * BHD + bh) * SEQ * HD;
    const __nv_bfloat16* Kh = g_ph + (size_t)(1 * BHD + bh) * SEQ * HD;
    const __nv_bfloat16* Kl = g_pl + (size_t)(1 * BHD + bh) * SEQ * HD;
    const __half*        Vf = g_vf16 + (size_t)bh * SEQ * HD;

    extern __shared__ char smc[];
    const uint32_t sb = smem_u32(smc);
    unsigned char* msh = (unsigned char*)(smc + S_MSK);

    const int tid  = threadIdx.x;
    const int warp = tid >> 5;
    const int lane = tid & 31;
    const int lane4 = lane >> 2, lanem = lane & 3;

    for (int o = tid; o < WR; o += 256) {
        const int t = base + o;
        msh[o] = (t >= 0 && t < SEQ && mask[t * BATCH + b] == 0) ? 1 : 0;
    }
#pragma unroll
    for (int it = 0; it < 10; it++) {
        const int idx = tid + 256 * it;
        const int row = idx >> 3, g = idx & 7;
        const int t = base + row;
        const int ok = (t >= 0 && t < SEQ);
        const int tc = ok ? t : 0;
        const int sz = ok ? 16 : 0;
        cp16z(sb + S_KH + row * KSTB + g * 16, Kh + (size_t)tc * HD + g * 8, sz);
        cp16z(sb + S_KL + row * KSTB + g * 16, Kl + (size_t)tc * HD + g * 8, sz);
    }
#pragma unroll
    for (int it = 0; it < 2; it++) {
        const int idx = tid + 256 * it;
        const int row = idx >> 3, g = idx & 7;
        cp16(sb + S_QH + row * KSTB + g * 16, Qh + (size_t)(s0 + row) * HD + g * 8);
        cp16(sb + S_QL + row * KSTB + g * 16, Ql + (size_t)(s0 + row) * HD + g * 8);
    }
    CP_COMMIT();
    CP_WAIT0();
    __syncthreads();

    // ---- GEMM1: S = Q K^T (bf16x3) with warp-uniform band-skip ----
    const int mw = warp >> 2;
    const int nw = warp & 3;
    const uint32_t a_off = (uint32_t)(lane & 15) * KSTB + (uint32_t)(lane >> 4) * 16;
    const uint32_t b_off = (uint32_t)((((lane >> 4) & 1) << 3) + (lane & 7)) * KSTB
                         + (uint32_t)((lane >> 3) & 1) * 16;

    float c1[2][10][4];
#pragma unroll
    for (int i = 0; i < 2; i++)
#pragma unroll
        for (int j = 0; j < 10; j++)
#pragma unroll
            for (int e = 0; e < 4; e++) c1[i][j][e] = 0.f;

#pragma unroll
    for (int kt = 0; kt < 4; kt++) {
        uint32_t Ah[2][4], Al[2][4];
#pragma unroll
        for (int mt = 0; mt < 2; mt++) {
            const uint32_t qa = sb + S_QH + (uint32_t)(mw * 32 + mt * 16) * KSTB
                              + a_off + kt * 32;
            ldm_x4(Ah[mt], qa);
            ldm_x4(Al[mt], qa + (S_QL - S_QH));
        }
#pragma unroll
        for (int np = 0; np < 5; np++) {
            const int cL = nw * 80 + np * 16;
            if (cL + 15 < mw * 32 || cL > mw * 32 + 287) continue;
            const uint32_t ka = sb + S_KH + (uint32_t)(cL) * KSTB
                              + b_off + kt * 32;
            uint32_t rh[4], rl[4];
            ldm_x4(rh, ka);
            ldm_x4(rl, ka + (S_KL - S_KH));
#pragma unroll
            for (int j = 0; j < 2; j++) {
                const int nt = np * 2 + j;
                const uint32_t bh0 = rh[2 * j], bh1 = rh[2 * j + 1];
                const uint32_t bl0 = rl[2 * j], bl1 = rl[2 * j + 1];
                mma_bf16(c1[0][nt], Ah[0], bh0, bh1);
                mma_bf16(c1[1][nt], Ah[1], bh0, bh1);
                mma_bf16(c1[0][nt], Al[0], bh0, bh1);
                mma_bf16(c1[1][nt], Al[1], bh0, bh1);
                mma_bf16(c1[0][nt], Ah[0], bl0, bl1);
                mma_bf16(c1[1][nt], Ah[1], bl0, bl1);
            }
        }
    }
    __syncthreads();

#pragma unroll
    for (int it = 0; it < 10; it++) {
        const int idx = tid + 256 * it;
        const int row = idx >> 3, g = idx & 7;
        const int t = base + row;
        const int ok = (t >= 0 && t < SEQ);
        const int tc = ok ? t : 0;
        const int sz = ok ? 16 : 0;
        cp16z(sb + S_VF + row * KSTB + g * 16, Vf + (size_t)tc * HD + g * 8, sz);
    }
    CP_COMMIT();

    // ---- band/mask epilogue on fragments ----
    const int r0w = mw * 32 + lane4;
    const int c0w = nw * 80 + 2 * lanem;
    uint32_t vb[2][2] = {{0u, 0u}, {0u, 0u}};
#pragma unroll
    for (int mt = 0; mt < 2; mt++)
#pragma unroll
        for (int nt = 0; nt < 10; nt++)
#pragma unroll
            for (int e = 0; e < 4; e++) {
                const int eh = e >> 1, el = e & 1;
                const int r = r0w + mt * 16 + eh * 8;
                const int cc = c0w + nt * 8 + el;
                float s = c1[mt][nt][e];
                const bool inband = (cc >= r) && (cc <= r + 256);
                const bool valid  = inband && msh[cc];
                if (!inband)      s = -1e30f;
                else if (!valid)  s = MINSC;
                c1[mt][nt][e] = s;
                if (valid) vb[mt][eh] |= 1u << (nt * 2 + el);
            }

    // ---- online softmax: warp-local max + exp + local sums, ONE barrier ----
    float pm[2][2] = {{-3e38f, -3e38f}, {-3e38f, -3e38f}};
#pragma unroll
    for (int mt = 0; mt < 2; mt++)
#pragma unroll
        for (int nt = 0; nt < 10; nt++)
#pragma unroll
            for (int e = 0; e < 4; e++)
                pm[mt][e >> 1] = fmaxf(pm[mt][e >> 1], c1[mt][nt][e]);
#pragma unroll
    for (int mt = 0; mt < 2; mt++)
#pragma unroll
        for (int eh = 0; eh < 2; eh++) {
            pm[mt][eh] = fmaxf(pm[mt][eh], __shfl_xor_sync(0xffffffffu, pm[mt][eh], 1));
            pm[mt][eh] = fmaxf(pm[mt][eh], __shfl_xor_sync(0xffffffffu, pm[mt][eh], 2));
        }

    float ps[2][2] = {{0.f, 0.f}, {0.f, 0.f}};
#pragma unroll
    for (int mt = 0; mt < 2; mt++)
#pragma unroll
        for (int nt = 0; nt < 10; nt++)
#pragma unroll
            for (int e = 0; e < 4; e++) {
                const float ex = __expf(c1[mt][nt][e] - pm[mt][e >> 1]);
                c1[mt][nt][e] = ex;
                ps[mt][e >> 1] += ex;
            }
#pragma unroll
    for (int mt = 0; mt < 2; mt++)
#pragma unroll
        for (int eh = 0; eh < 2; eh++) {
            ps[mt][eh] += __shfl_xor_sync(0xffffffffu, ps[mt][eh], 1);
            ps[mt][eh] += __shfl_xor_sync(0xffffffffu, ps[mt][eh], 2);
        }
    if (lanem == 0) {
#pragma unroll
        for (int mt = 0; mt < 2; mt++)
#pragma unroll
            for (int eh = 0; eh < 2; eh++) {
                const int r = r0w + mt * 16 + eh * 8;
                *(float*)(smc + S_RMAX + (r * 4 + nw) * 4) = pm[mt][eh];
                *(float*)(smc + S_RSUM + (r * 4 + nw) * 4) = ps[mt][eh];
            }
    }
    __syncthreads();

    // ---- rescale to global softmax; write probs gmem + fp16 P smem ----
#pragma unroll
    for (int mt = 0; mt < 2; mt++)
#pragma unroll
        for (int eh = 0; eh < 2; eh++) {
            const int r = r0w + mt * 16 + eh * 8;
            const float* rp = (const float*)(smc + S_RMAX + r * 16);
            const float* sp = (const float*)(smc + S_RSUM + r * 16);
            const float gm = fmaxf(fmaxf(rp[0], rp[1]), fmaxf(rp[2], rp[3]));
            const float denom = sp[0] * __expf(rp[0] - gm)
                              + sp[1] * __expf(rp[1] - gm)
                              + sp[2] * __expf(rp[2] - gm)
                              + sp[3] * __expf(rp[3] - gm);
            const float sc = __expf(pm[mt][eh] - gm) / denom;
            float* prow = probs + ((size_t)bh * SEQ + (s0 + r)) * WIN;
            const uint32_t vbits = vb[mt][eh];
            char* pbf = smc + S_PF + r * PSTB;
#pragma unroll
            for (int nt = 0; nt < 10; nt++) {
                float p0 = c1[mt][nt][eh * 2 + 0] * sc;
                float p1 = c1[mt][nt][eh * 2 + 1] * sc;
                if (!(vbits & (1u << (nt * 2 + 0)))) p0 = 0.f;
                if (!(vbits & (1u << (nt * 2 + 1)))) p1 = 0.f;
                const int cc = c0w + nt * 8;
                if (cc >= r && cc <= r + 256)         prow[cc - r]     = p0;
                if (cc + 1 >= r && cc + 1 <= r + 256) prow[cc + 1 - r] = p1;
                *(uint32_t*)(pbf + cc * 2) = pkh2(p0, p1);
            }
        }

    CP_WAIT0();
    __syncthreads();

    // ---- GEMM2: O = P V (single fp16) with band-skip ----
    const int mw2 = warp >> 1;
    const int nw2 = warp & 1;
    float c2[4][4];
#pragma unroll
    for (int j = 0; j < 4; j++)
#pragma unroll
        for (int e = 0; e < 4; e++) c2[j][e] = 0.f;

    const uint32_t pa_off = (uint32_t)(lane & 15) * PSTB + (uint32_t)(lane >> 4) * 16;
    const uint32_t vrow   = (lane & 7) + (((lane >> 3) & 1) << 3);
    const uint32_t vcoff  = (uint32_t)(nw2 * 32 + ((lane >> 4) << 3)) * 2;

#pragma unroll 4
    for (int kt = 0; kt < 20; kt++) {
        const int kc = kt * 16;
        if (kc + 15 < mw2 * 16 || kc > mw2 * 16 + 271) continue;

        uint32_t Ph[4];
        ldm_x4(Ph, sb + S_PF + (uint32_t)(mw2 * 16) * PSTB + pa_off + kc * 2);

        uint32_t vh0[4], vh1[4];
        const uint32_t va = sb + S_VF + (kc + vrow) * KSTB + vcoff;
        ldm_x4_t(vh0, va);
        ldm_x4_t(vh1, va + 32);

#pragma unroll
        for (int nt = 0; nt < 4; nt++) {
            const uint32_t* ph = (nt < 2) ? vh0 : vh1;
            const int j = nt & 1;
            mma_f16(c2[nt], Ph, ph[2 * j], ph[2 * j + 1]);
        }
    }

#pragma unroll
    for (int nt = 0; nt < 4; nt++) {
        const int d = nw2 * 32 + nt * 8 + 2 * lanem;
#pragma unroll
        for (int eh = 0; eh < 2; eh++) {
            const int r = mw2 * 16 + lane4 + eh * 8;
            *(float2*)(out + ((size_t)(s0 + r) * BATCH + b) * HID + head * HD + d) =
                make_float2(c2[nt][eh * 2], c2[nt][eh * 2 + 1]);
        }
    }
}

// ---------------- launch ------------------------------------------------------
extern "C" void kernel_launch(void* const* d_in, const int* in_sizes, int n_in,
                              void* d_out, int out_size)
{
    const float* q_in = (const float*)d_in[0];
    const float* k_in = (const float*)d_in[1];
    const float* v_in = (const float*)d_in[2];
    const unsigned char* mask = (const unsigned char*)d_in[3];
    const float* Wq = (const float*)d_in[4];
    const float* bq = (const float*)d_in[5];
    const float* Wk = (const float*)d_in[6];
    const float* bk = (const float*)d_in[7];
    const float* Wv = (const float*)d_in[8];
    const float* bv = (const float*)d_in[9];

    float* out   = (float*)d_out;
    float* probs = out + (size_t)SEQ * BATCH * HID;

    cudaFuncSetAttribute(proj_mma_kernel, cudaFuncAttributeMaxDynamicSharedMemorySize,
                         PROJ_SMEM);
    cudaFuncSetAttribute(attn_kernel, cudaFuncAttributeMaxDynamicSharedMemorySize,
                         ATT_SMEM);

    dim3 gc(XBLK8 + WBLK8, 3);
    convert_all<<<gc, 256>>>(q_in, k_in, v_in, Wq, Wk, Wv);

    dim3 gp(HID / PBN, ROWS / PBM, 3);
    proj_mma_kernel<<<gp, 256, PROJ_SMEM>>>(bq, bk, bv);

    dim3 ga(SEQ / TQ, BHD);
    attn_kernel<<<ga, 256, ATT_SMEM>>>(mask, out, probs);
}